// round 13
// baseline (speedup 1.0000x reference)
#include <cuda_runtime.h>
#include <cstdint>

// FusedSOSCascade: 8-section biquad cascade over x[128, 65536].
// Block-parallel IIR + warmup overlap + packed fma.rn.f32x2 + systolic skew
// + smem-staged I/O. R13: IN-PLACE smem staging (outputs overwrite the input
// slots after they are consumed) -> 32KB/block instead of 64KB -> 2 resident
// blocks/SM (16 warps/SM), doubling the warps that hide FMA/LDS latency.
// W=88 (measured rel_err 8.3e-5, threshold 1e-3).
// Skew: x(i) fed at iter i; output at iter i is y(i-8); stores 8-shifted.

#define KSEC 8
#define TLEN 65536
#define NCH  128
#define LCHUNK 128
#define WARMUP 88
#define NITER (WARMUP + LCHUNK + 8)          // 224 = 7 tiles of 32
#define NTILES 7
#define PAIRS_PER_CH (TLEN / (2 * LCHUNK))   // 256
#define TOTAL_THREADS (NCH * PAIRS_PER_CH)   // 32768
#define BLOCK_THREADS 128
#define WARP_SMEM_FLOATS 2048                // 64 blocks * 32 floats = 8KB

__device__ __forceinline__ uint64_t pack2(float lo, float hi) {
    uint64_t r;
    asm("mov.b64 %0, {%1, %2};" : "=l"(r) : "f"(lo), "f"(hi));
    return r;
}
__device__ __forceinline__ void unpack2(uint64_t v, float& lo, float& hi) {
    asm("mov.b64 {%0, %1}, %2;" : "=f"(lo), "=f"(hi) : "l"(v));
}
__device__ __forceinline__ uint64_t fma2(uint64_t a, uint64_t b, uint64_t c) {
    uint64_t d;
    asm("fma.rn.f32x2 %0, %1, %2, %3;" : "=l"(d) : "l"(a), "l"(b), "l"(c));
    return d;
}
__device__ __forceinline__ uint64_t mul2(uint64_t a, uint64_t b) {
    uint64_t d;
    asm("mul.rn.f32x2 %0, %1, %2;" : "=l"(d) : "l"(a), "l"(b));
    return d;
}

// Swizzled float offset of 16B unit k (0..7) in 128B block b (0..63):
// bank-disjoint for both the cooperative (per-block) and per-lane (block=2j)
// access patterns.
#define SWZ(b, k) ((b) * 32 + ((((k) ^ (((b) >> 1) & 7))) << 2))

// One skewed iteration; J literal 0..3. Section k reads stream k at slots
// i-1,i-2,i-3 and stream k+1 at i-1,i-2; writes slot i&3. ob[i&3] = G*y.
#define STEP(J, XIN) do {                                              \
    const int _c  = (J) & 3;                                           \
    const int _p1 = ((J) + 3) & 3;                                     \
    const int _p2 = ((J) + 2) & 3;                                     \
    const int _p3 = ((J) + 1) & 3;                                     \
    uint64_t _nw[KSEC];                                                \
    _Pragma("unroll")                                                  \
    for (int k = 0; k < KSEC; k++) {                                   \
        uint64_t _acc = fma2(B1[k], h[k][_p2], h[k][_p1]);             \
        _acc = fma2(B2[k],  h[k][_p3],     _acc);                      \
        _acc = fma2(NA1[k], h[k + 1][_p1], _acc);                      \
        _nw[k] = fma2(NA2[k], h[k + 1][_p2], _acc);                    \
    }                                                                  \
    h[0][_c] = (XIN);                                                  \
    _Pragma("unroll")                                                  \
    for (int k = 0; k < KSEC; k++) h[k + 1][_c] = _nw[k];              \
    ob[_c] = mul2(G, _nw[KSEC - 1]);                                   \
} while (0)

__global__ void __launch_bounds__(BLOCK_THREADS, 2)
sos_cascade_v10_kernel(const float* __restrict__ x,
                       const float* __restrict__ sos,
                       float* __restrict__ y)
{
    extern __shared__ float smem[];
    const int tid  = threadIdx.x;
    const int gwid = (blockIdx.x * BLOCK_THREADS + tid) >> 5;  // global warp
    const int lane = tid & 31;
    const int wblk = tid >> 5;                                 // warp in block

    float* s_buf = smem + wblk * WARP_SMEM_FLOATS;   // single in-place buffer

    const int ch = gwid >> 3;          // 8 warps per channel
    const int p0 = (gwid & 7) * 32;    // warp's first pair index

    uint64_t B1[KSEC], B2[KSEC], NA1[KSEC], NA2[KSEC], G;
    float Gs = 1.0f;
#pragma unroll
    for (int k = 0; k < KSEC; k++) {
        const float s0 = sos[k * 6 + 0];
        const float s1 = sos[k * 6 + 1];
        const float s2 = sos[k * 6 + 2];
        const float a0 = sos[k * 6 + 3];
        const float a1 = sos[k * 6 + 4];
        const float a2 = sos[k * 6 + 5];
        const float B1v  =  s1 / s0;
        const float B2v  =  s2 / s0;
        const float NA1v = -a1 / a0;
        const float NA2v = -a2 / a0;
        B1[k]  = pack2(B1v, B1v);
        B2[k]  = pack2(B2v, B2v);
        NA1[k] = pack2(NA1v, NA1v);
        NA2[k] = pack2(NA2v, NA2v);
        Gs *= s0 / a0;
    }
    G = pack2(Gs, Gs);

    uint64_t h[KSEC + 1][4];
#pragma unroll
    for (int m = 0; m <= KSEC; m++)
#pragma unroll
        for (int s = 0; s < 4; s++) h[m][s] = 0ull;
    uint64_t ob[4] = {0ull, 0ull, 0ull, 0ull};

    const float* xc = x + (size_t)ch * TLEN;
    float*       yc = y + (size_t)ch * TLEN;

    // Per-lane swizzled smem offsets (blocks 2*lane = A, 2*lane+1 = B).
    const int keyA  = lane & 7;
    const int baseA = (2 * lane) * 32;
    const int baseB = (2 * lane + 1) * 32;

#pragma unroll 1
    for (int tile = 0; tile < NTILES; tile++) {
        const int i0  = tile * 32;
        const int wst = p0 * 256 - WARMUP + i0;  // warp region start (samples)

        // ---- Cooperative gather: 64 x 128B blocks -> swizzled smem. ----
#pragma unroll
        for (int I = 0; I < 16; I++) {
            const int b = 4 * I + (lane >> 3);
            const int k = lane & 7;
            const int t = wst + b * 128 + k * 4;
            float4 v = make_float4(0.f, 0.f, 0.f, 0.f);
            if (t >= 0 && t < TLEN)
                v = *reinterpret_cast<const float4*>(xc + t);
            *reinterpret_cast<float4*>(s_buf + SWZ(b, k)) = v;
        }
        __syncwarp();

        // ---- Compute 8 groups (32 iterations); outputs overwrite the
        //      consumed input slots (each lane touches only its own blocks).
        const bool storing = (tile >= 3);
#pragma unroll
        for (int gb = 0; gb < 8; gb++) {
            const int u = (gb ^ keyA) << 2;
            const float4 xa = *reinterpret_cast<const float4*>(s_buf + baseA + u);
            const float4 xb = *reinterpret_cast<const float4*>(s_buf + baseB + u);
            STEP(0, pack2(xa.x, xb.x));
            STEP(1, pack2(xa.y, xb.y));
            STEP(2, pack2(xa.z, xb.z));
            STEP(3, pack2(xa.w, xb.w));
            if (storing) {
                float a0f, b0f, a1f, b1f, a2f, b2f, a3f, b3f;
                unpack2(ob[0], a0f, b0f);
                unpack2(ob[1], a1f, b1f);
                unpack2(ob[2], a2f, b2f);
                unpack2(ob[3], a3f, b3f);
                *reinterpret_cast<float4*>(s_buf + baseA + u) =
                    make_float4(a0f, a1f, a2f, a3f);
                *reinterpret_cast<float4*>(s_buf + baseB + u) =
                    make_float4(b0f, b1f, b2f, b3f);
            }
        }

        // ---- Cooperative scatter of the tile's outputs. ----
        if (storing) {
            __syncwarp();
            const int wso = wst - 8;   // stored times = input times - 8
#pragma unroll
            for (int I = 0; I < 16; I++) {
                const int b = 4 * I + (lane >> 3);
                const int k = lane & 7;
                const float4 v =
                    *reinterpret_cast<const float4*>(s_buf + SWZ(b, k));
                *reinterpret_cast<float4*>(yc + wso + b * 128 + k * 4) = v;
            }
        }
        __syncwarp();
    }
}

extern "C" void kernel_launch(void* const* d_in, const int* in_sizes, int n_in,
                              void* d_out, int out_size)
{
    const float* x   = (const float*)d_in[0];
    const float* sos = (const float*)d_in[1];
    float*       y   = (float*)d_out;

    const int smem_bytes = 4 * WARP_SMEM_FLOATS * (int)sizeof(float); // 32KB
    cudaFuncSetAttribute(sos_cascade_v10_kernel,
                         cudaFuncAttributeMaxDynamicSharedMemorySize,
                         smem_bytes);
    const int grid = TOTAL_THREADS / BLOCK_THREADS;   // 256 blocks
    sos_cascade_v10_kernel<<<grid, BLOCK_THREADS, smem_bytes>>>(x, sos, y);
}

// round 14
// speedup vs baseline: 1.0636x; 1.0636x over previous
#include <cuda_runtime.h>
#include <cstdint>

// FusedSOSCascade: 8-section biquad cascade over x[128, 65536].
// Block-parallel IIR + warmup overlap + packed fma.rn.f32x2 + systolic skew
// + in-place smem-staged I/O. R14: SINGLE-WAVE PACKING — the 1024 warp-jobs
// go out as 128 blocks x 8 warps (<=148 SMs) instead of 256 x 4, removing the
// 2-wave makespan (v9/v10 ran 108 SMs twice serially) and giving every SMSP
// 2 resident warps for latency hiding the whole run.
// W=88 (measured rel_err 8.3e-5, threshold 1e-3).
// Skew: x(i) fed at iter i; output at iter i is y(i-8); stores 8-shifted.

#define KSEC 8
#define TLEN 65536
#define NCH  128
#define LCHUNK 128
#define WARMUP 88
#define NITER (WARMUP + LCHUNK + 8)          // 224 = 7 tiles of 32
#define NTILES 7
#define PAIRS_PER_CH (TLEN / (2 * LCHUNK))   // 256
#define TOTAL_THREADS (NCH * PAIRS_PER_CH)   // 32768
#define BLOCK_THREADS 256                    // 8 warps -> grid = 128 (1 wave)
#define WARP_SMEM_FLOATS 2048                // 64 blocks * 32 floats = 8KB

__device__ __forceinline__ uint64_t pack2(float lo, float hi) {
    uint64_t r;
    asm("mov.b64 %0, {%1, %2};" : "=l"(r) : "f"(lo), "f"(hi));
    return r;
}
__device__ __forceinline__ void unpack2(uint64_t v, float& lo, float& hi) {
    asm("mov.b64 {%0, %1}, %2;" : "=f"(lo), "=f"(hi) : "l"(v));
}
__device__ __forceinline__ uint64_t fma2(uint64_t a, uint64_t b, uint64_t c) {
    uint64_t d;
    asm("fma.rn.f32x2 %0, %1, %2, %3;" : "=l"(d) : "l"(a), "l"(b), "l"(c));
    return d;
}
__device__ __forceinline__ uint64_t mul2(uint64_t a, uint64_t b) {
    uint64_t d;
    asm("mul.rn.f32x2 %0, %1, %2;" : "=l"(d) : "l"(a), "l"(b));
    return d;
}

// Swizzled float offset of 16B unit k (0..7) in 128B block b (0..63):
// bank-disjoint for both the cooperative (per-block) and per-lane (block=2j)
// access patterns.
#define SWZ(b, k) ((b) * 32 + ((((k) ^ (((b) >> 1) & 7))) << 2))

// One skewed iteration; J literal 0..3. Section k reads stream k at slots
// i-1,i-2,i-3 and stream k+1 at i-1,i-2; writes slot i&3. ob[i&3] = G*y.
#define STEP(J, XIN) do {                                              \
    const int _c  = (J) & 3;                                           \
    const int _p1 = ((J) + 3) & 3;                                     \
    const int _p2 = ((J) + 2) & 3;                                     \
    const int _p3 = ((J) + 1) & 3;                                     \
    uint64_t _nw[KSEC];                                                \
    _Pragma("unroll")                                                  \
    for (int k = 0; k < KSEC; k++) {                                   \
        uint64_t _acc = fma2(B1[k], h[k][_p2], h[k][_p1]);             \
        _acc = fma2(B2[k],  h[k][_p3],     _acc);                      \
        _acc = fma2(NA1[k], h[k + 1][_p1], _acc);                      \
        _nw[k] = fma2(NA2[k], h[k + 1][_p2], _acc);                    \
    }                                                                  \
    h[0][_c] = (XIN);                                                  \
    _Pragma("unroll")                                                  \
    for (int k = 0; k < KSEC; k++) h[k + 1][_c] = _nw[k];              \
    ob[_c] = mul2(G, _nw[KSEC - 1]);                                   \
} while (0)

__global__ void __launch_bounds__(BLOCK_THREADS, 1)
sos_cascade_v11_kernel(const float* __restrict__ x,
                       const float* __restrict__ sos,
                       float* __restrict__ y)
{
    extern __shared__ float smem[];
    const int tid  = threadIdx.x;
    const int gwid = (blockIdx.x * BLOCK_THREADS + tid) >> 5;  // global warp
    const int lane = tid & 31;
    const int wblk = tid >> 5;                                 // warp in block

    float* s_buf = smem + wblk * WARP_SMEM_FLOATS;   // in-place buffer, 8KB

    const int ch = gwid >> 3;          // 8 warps per channel
    const int p0 = (gwid & 7) * 32;    // warp's first pair index

    uint64_t B1[KSEC], B2[KSEC], NA1[KSEC], NA2[KSEC], G;
    float Gs = 1.0f;
#pragma unroll
    for (int k = 0; k < KSEC; k++) {
        const float s0 = sos[k * 6 + 0];
        const float s1 = sos[k * 6 + 1];
        const float s2 = sos[k * 6 + 2];
        const float a0 = sos[k * 6 + 3];
        const float a1 = sos[k * 6 + 4];
        const float a2 = sos[k * 6 + 5];
        const float B1v  =  s1 / s0;
        const float B2v  =  s2 / s0;
        const float NA1v = -a1 / a0;
        const float NA2v = -a2 / a0;
        B1[k]  = pack2(B1v, B1v);
        B2[k]  = pack2(B2v, B2v);
        NA1[k] = pack2(NA1v, NA1v);
        NA2[k] = pack2(NA2v, NA2v);
        Gs *= s0 / a0;
    }
    G = pack2(Gs, Gs);

    uint64_t h[KSEC + 1][4];
#pragma unroll
    for (int m = 0; m <= KSEC; m++)
#pragma unroll
        for (int s = 0; s < 4; s++) h[m][s] = 0ull;
    uint64_t ob[4] = {0ull, 0ull, 0ull, 0ull};

    const float* xc = x + (size_t)ch * TLEN;
    float*       yc = y + (size_t)ch * TLEN;

    // Per-lane swizzled smem offsets (blocks 2*lane = A, 2*lane+1 = B).
    const int keyA  = lane & 7;
    const int baseA = (2 * lane) * 32;
    const int baseB = (2 * lane + 1) * 32;

#pragma unroll 1
    for (int tile = 0; tile < NTILES; tile++) {
        const int i0  = tile * 32;
        const int wst = p0 * 256 - WARMUP + i0;  // warp region start (samples)

        // ---- Cooperative gather: 64 x 128B blocks -> swizzled smem. ----
#pragma unroll
        for (int I = 0; I < 16; I++) {
            const int b = 4 * I + (lane >> 3);
            const int k = lane & 7;
            const int t = wst + b * 128 + k * 4;
            float4 v = make_float4(0.f, 0.f, 0.f, 0.f);
            if (t >= 0 && t < TLEN)
                v = *reinterpret_cast<const float4*>(xc + t);
            *reinterpret_cast<float4*>(s_buf + SWZ(b, k)) = v;
        }
        __syncwarp();

        // ---- Compute 8 groups (32 iterations); outputs overwrite the
        //      consumed input slots (each lane touches only its own blocks).
        const bool storing = (tile >= 3);
#pragma unroll
        for (int gb = 0; gb < 8; gb++) {
            const int u = (gb ^ keyA) << 2;
            const float4 xa = *reinterpret_cast<const float4*>(s_buf + baseA + u);
            const float4 xb = *reinterpret_cast<const float4*>(s_buf + baseB + u);
            STEP(0, pack2(xa.x, xb.x));
            STEP(1, pack2(xa.y, xb.y));
            STEP(2, pack2(xa.z, xb.z));
            STEP(3, pack2(xa.w, xb.w));
            if (storing) {
                float a0f, b0f, a1f, b1f, a2f, b2f, a3f, b3f;
                unpack2(ob[0], a0f, b0f);
                unpack2(ob[1], a1f, b1f);
                unpack2(ob[2], a2f, b2f);
                unpack2(ob[3], a3f, b3f);
                *reinterpret_cast<float4*>(s_buf + baseA + u) =
                    make_float4(a0f, a1f, a2f, a3f);
                *reinterpret_cast<float4*>(s_buf + baseB + u) =
                    make_float4(b0f, b1f, b2f, b3f);
            }
        }

        // ---- Cooperative scatter of the tile's outputs. ----
        if (storing) {
            __syncwarp();
            const int wso = wst - 8;   // stored times = input times - 8
#pragma unroll
            for (int I = 0; I < 16; I++) {
                const int b = 4 * I + (lane >> 3);
                const int k = lane & 7;
                const float4 v =
                    *reinterpret_cast<const float4*>(s_buf + SWZ(b, k));
                *reinterpret_cast<float4*>(yc + wso + b * 128 + k * 4) = v;
            }
        }
        __syncwarp();
    }
}

extern "C" void kernel_launch(void* const* d_in, const int* in_sizes, int n_in,
                              void* d_out, int out_size)
{
    const float* x   = (const float*)d_in[0];
    const float* sos = (const float*)d_in[1];
    float*       y   = (float*)d_out;

    const int smem_bytes = 8 * WARP_SMEM_FLOATS * (int)sizeof(float); // 64KB
    cudaFuncSetAttribute(sos_cascade_v11_kernel,
                         cudaFuncAttributeMaxDynamicSharedMemorySize,
                         smem_bytes);
    const int grid = TOTAL_THREADS / BLOCK_THREADS;   // 128 blocks, 1 wave
    sos_cascade_v11_kernel<<<grid, BLOCK_THREADS, smem_bytes>>>(x, sos, y);
}